// round 13
// baseline (speedup 1.0000x reference)
#include <cuda_runtime.h>
#include <cuda_bf16.h>
#include <cstdint>

// velocity = MLP(concat(zone_embedding, person_attrs, time_vec)).
// GCN layers are dead code w.r.t. the output; person/time layer-1
// contributions are row-constant, folded into c1 in-kernel.
//
// R13: single kernel. Two-phase fragment packing (coalesced raw-W -> smem,
// LDS+split2 -> regs, STS frags into the same smem region), fold chains
// (u->tv->c1) overlapped under the packing barriers. Mainloop = R10's bf16
// 3-term-split mma.m16n8k16 with accumulators SPLIT per (mt,kt): layer1
// chains 6->3, layer2 12->6, layer3 6->3 serial HMMAs, doubling independent
// tensor chains per warp (the ~20cyc/inst stall R12's profile implied).

#define HID 32
#define H1  64
#define TPB 128            // 4 warps, 32 rows/warp, 128 rows/block

typedef uint32_t u32;

// pack pair (x0 -> low half, x1 -> high half) into bf16x2 hi, residual lo.
__device__ __forceinline__ void split2(float x0, float x1, u32& hi, u32& lo) {
    asm("cvt.rn.bf16x2.f32 %0, %1, %2;" : "=r"(hi) : "f"(x1), "f"(x0));
    float h0 = __uint_as_float(hi << 16);
    float h1 = __uint_as_float(hi & 0xffff0000u);
    float r0 = x0 - h0;
    float r1 = x1 - h1;
    asm("cvt.rn.bf16x2.f32 %0, %1, %2;" : "=r"(lo) : "f"(r1), "f"(r0));
}

__device__ __forceinline__ void mma_bf16(float d[4], const u32 a[4], u32 b0, u32 b1) {
    asm("mma.sync.aligned.m16n8k16.row.col.f32.bf16.bf16.f32 "
        "{%0,%1,%2,%3}, {%4,%5,%6,%7}, {%8,%9}, {%0,%1,%2,%3};"
        : "+f"(d[0]), "+f"(d[1]), "+f"(d[2]), "+f"(d[3])
        : "r"(a[0]), "r"(a[1]), "r"(a[2]), "r"(a[3]), "r"(b0), "r"(b1));
}

// ---------------------------------------------------------------------------
__global__ void __launch_bounds__(TPB)
velo_kernel(const float* __restrict__ emb,
            const float* __restrict__ t,   const float* __restrict__ pa,
            const float* __restrict__ Wt1, const float* __restrict__ bt1,
            const float* __restrict__ Wt2, const float* __restrict__ bt2,
            const float* __restrict__ Wd1, const float* __restrict__ bd1,
            const float* __restrict__ Wd2, const float* __restrict__ bd2,
            const float* __restrict__ Wd3, const float* __restrict__ bd3,
            float* __restrict__ out, int nrows)
{
    __shared__ __align__(16) uint4 s_frag[1280];    // 20KB: raw W, then frags
    __shared__ __align__(16) float s_c1[64];
    __shared__ float s_u[16], s_tv[16];
    float* s_raw = reinterpret_cast<float*>(s_frag);

    const int tid  = threadIdx.x;
    const int warp = tid >> 5;
    const int lane = tid & 31;
    const int g = lane >> 2, tq = lane & 3;
    const int row_base = blockIdx.x * 128 + warp * 32;

    // ---- independent front loads: z rows, bd2/bd3 bias regs ----
    const float2 zero2 = make_float2(0.0f, 0.0f);
    int ra[2], rb[2];
    #pragma unroll
    for (int mt = 0; mt < 2; ++mt) { ra[mt] = row_base + 16 * mt + g; rb[mt] = ra[mt] + 8; }

    u32 A1h[2][2][4], A1l[2][2][4];
    if (row_base < nrows) {
        #pragma unroll
        for (int mt = 0; mt < 2; ++mt) {
            #pragma unroll
            for (int kt = 0; kt < 2; ++kt) {
                float2 p0 = (ra[mt] < nrows) ? *reinterpret_cast<const float2*>(emb + (size_t)ra[mt] * 32 + 16 * kt + 2 * tq)     : zero2;
                float2 p1 = (rb[mt] < nrows) ? *reinterpret_cast<const float2*>(emb + (size_t)rb[mt] * 32 + 16 * kt + 2 * tq)     : zero2;
                float2 p2 = (ra[mt] < nrows) ? *reinterpret_cast<const float2*>(emb + (size_t)ra[mt] * 32 + 16 * kt + 8 + 2 * tq) : zero2;
                float2 p3 = (rb[mt] < nrows) ? *reinterpret_cast<const float2*>(emb + (size_t)rb[mt] * 32 + 16 * kt + 8 + 2 * tq) : zero2;
                split2(p0.x, p0.y, A1h[mt][kt][0], A1l[mt][kt][0]);
                split2(p1.x, p1.y, A1h[mt][kt][1], A1l[mt][kt][1]);
                split2(p2.x, p2.y, A1h[mt][kt][2], A1l[mt][kt][2]);
                split2(p3.x, p3.y, A1h[mt][kt][3], A1l[mt][kt][3]);
            }
        }
    }
    float2 bb_r[4], b3_r[4];
    #pragma unroll
    for (int nt = 0; nt < 4; ++nt) {
        bb_r[nt] = *reinterpret_cast<const float2*>(bd2 + 8 * nt + 2 * tq);
        b3_r[nt] = *reinterpret_cast<const float2*>(bd3 + 8 * nt + 2 * tq);
    }

    // ---- phase 1: coalesced raw weights -> smem; u fold ----
    {
        const float4* w1v = reinterpret_cast<const float4*>(Wd1);  // zone rows: first 512 f4
        const float4* w2v = reinterpret_cast<const float4*>(Wd2);
        const float4* w3v = reinterpret_cast<const float4*>(Wd3);
        float4* rw = reinterpret_cast<float4*>(s_raw);
        #pragma unroll
        for (int i = tid; i < 512; i += TPB)  rw[i]        = w1v[i];
        #pragma unroll
        for (int i = tid; i < 512; i += TPB)  rw[512 + i]  = w2v[i];
        #pragma unroll
        for (int i = tid; i < 256; i += TPB)  rw[1024 + i] = w3v[i];
    }
    if (tid < 16) s_u[tid] = fmaxf(fmaf(t[0], Wt1[tid], bt1[tid]), 0.0f);
    __syncthreads();

    // ---- phase 2: tv fold (warp 0); all threads pack frags into regs ----
    if (tid < 16) {
        float a = bt2[tid];
        #pragma unroll
        for (int i = 0; i < 16; i++) a = fmaf(s_u[i], Wt2[i * 16 + tid], a);
        s_tv[tid] = a;
    }
    uint4 fr[10];
    #pragma unroll
    for (int p = 0; p < 10; ++p) {
        int idx = tid + p * TPB;
        int base, stride, nt, kt, ln;
        if (idx < 512)       { int s = idx;        ln = s & 31; int q = s >> 5; nt = q >> 1; kt = q & 1; base = 0;    stride = 64; }
        else if (idx < 1024) { int s = idx - 512;  ln = s & 31; int q = s >> 5; nt = q >> 2; kt = q & 3; base = 2048; stride = 32; }
        else                 { int s = idx - 1024; ln = s & 31; int q = s >> 5; nt = q >> 1; kt = q & 1; base = 4096; stride = 32; }
        int gg = ln >> 2, tt = ln & 3;
        int col  = 8 * nt + gg;
        int krow = 16 * kt + 2 * tt;
        float w00 = s_raw[base + (krow    ) * stride + col];
        float w01 = s_raw[base + (krow + 1) * stride + col];
        float w10 = s_raw[base + (krow + 8) * stride + col];
        float w11 = s_raw[base + (krow + 9) * stride + col];
        split2(w00, w01, fr[p].x, fr[p].z);
        split2(w10, w11, fr[p].y, fr[p].w);
    }
    __syncthreads();

    // ---- phase 3: c1 fold (global Wd1 rows 32..55); STS frags ----
    if (tid < H1) {
        float a = bd1[tid];
        #pragma unroll
        for (int p = 0; p < 8; p++)  a = fmaf(pa[p], Wd1[(HID + p) * H1 + tid], a);
        #pragma unroll
        for (int i = 0; i < 16; i++) a = fmaf(s_tv[i], Wd1[(HID + 8 + i) * H1 + tid], a);
        s_c1[tid] = a;
    }
    #pragma unroll
    for (int p = 0; p < 10; ++p) s_frag[tid + p * TPB] = fr[p];
    __syncthreads();

    if (row_base >= nrows) return;      // after the last barrier

    // ---- layer1 (K=32, N=64): accumulators split per (mt,kt), chains of 3 ----
    u32 A2h[2][4][4], A2l[2][4][4];
    #pragma unroll
    for (int nt = 0; nt < 8; ++nt) {
        float d[2][2][4] = {};
        #pragma unroll
        for (int kt = 0; kt < 2; ++kt) {
            uint4 B = s_frag[(nt * 2 + kt) * 32 + lane];
            #pragma unroll
            for (int mt = 0; mt < 2; ++mt) {
                mma_bf16(d[mt][kt], A1h[mt][kt], B.x, B.y);
                mma_bf16(d[mt][kt], A1h[mt][kt], B.z, B.w);
                mma_bf16(d[mt][kt], A1l[mt][kt], B.x, B.y);
            }
        }
        float2 cb = *reinterpret_cast<const float2*>(s_c1 + 8 * nt + 2 * tq);
        int kt2 = nt >> 1, off = (nt & 1) * 2;
        #pragma unroll
        for (int mt = 0; mt < 2; ++mt) {
            float h0 = fmaxf(d[mt][0][0] + d[mt][1][0] + cb.x, 0.0f);
            float h1 = fmaxf(d[mt][0][1] + d[mt][1][1] + cb.y, 0.0f);
            float h2 = fmaxf(d[mt][0][2] + d[mt][1][2] + cb.x, 0.0f);
            float h3 = fmaxf(d[mt][0][3] + d[mt][1][3] + cb.y, 0.0f);
            split2(h0, h1, A2h[mt][kt2][off],     A2l[mt][kt2][off]);
            split2(h2, h3, A2h[mt][kt2][off + 1], A2l[mt][kt2][off + 1]);
        }
    }

    // ---- layer2 (K=64, N=32): acc split per (mt, kt parity), chains of 6 ----
    u32 A3h[2][2][4], A3l[2][2][4];
    #pragma unroll
    for (int nt = 0; nt < 4; ++nt) {
        float d[2][2][4] = {};
        #pragma unroll
        for (int kt = 0; kt < 4; ++kt) {
            uint4 B = s_frag[512 + (nt * 4 + kt) * 32 + lane];
            #pragma unroll
            for (int mt = 0; mt < 2; ++mt) {
                mma_bf16(d[mt][kt & 1], A2h[mt][kt], B.x, B.y);
                mma_bf16(d[mt][kt & 1], A2h[mt][kt], B.z, B.w);
                mma_bf16(d[mt][kt & 1], A2l[mt][kt], B.x, B.y);
            }
        }
        float2 bb = bb_r[nt];
        int kt3 = nt >> 1, off = (nt & 1) * 2;
        #pragma unroll
        for (int mt = 0; mt < 2; ++mt) {
            float h0 = fmaxf(d[mt][0][0] + d[mt][1][0] + bb.x, 0.0f);
            float h1 = fmaxf(d[mt][0][1] + d[mt][1][1] + bb.y, 0.0f);
            float h2 = fmaxf(d[mt][0][2] + d[mt][1][2] + bb.x, 0.0f);
            float h3 = fmaxf(d[mt][0][3] + d[mt][1][3] + bb.y, 0.0f);
            split2(h0, h1, A3h[mt][kt3][off],     A3l[mt][kt3][off]);
            split2(h2, h3, A3h[mt][kt3][off + 1], A3l[mt][kt3][off + 1]);
        }
    }

    // ---- layer3 (K=32, N=32): acc split per (mt,kt), chains of 3; store ----
    #pragma unroll
    for (int nt = 0; nt < 4; ++nt) {
        float d[2][2][4] = {};
        #pragma unroll
        for (int kt = 0; kt < 2; ++kt) {
            uint4 B = s_frag[1024 + (nt * 2 + kt) * 32 + lane];
            #pragma unroll
            for (int mt = 0; mt < 2; ++mt) {
                mma_bf16(d[mt][kt], A3h[mt][kt], B.x, B.y);
                mma_bf16(d[mt][kt], A3h[mt][kt], B.z, B.w);
                mma_bf16(d[mt][kt], A3l[mt][kt], B.x, B.y);
            }
        }
        float2 b3 = b3_r[nt];
        #pragma unroll
        for (int mt = 0; mt < 2; ++mt) {
            if (ra[mt] < nrows)
                *reinterpret_cast<float2*>(out + (size_t)ra[mt] * 32 + 8 * nt + 2 * tq) =
                    make_float2(d[mt][0][0] + d[mt][1][0] + b3.x, d[mt][0][1] + d[mt][1][1] + b3.y);
            if (rb[mt] < nrows)
                *reinterpret_cast<float2*>(out + (size_t)rb[mt] * 32 + 8 * nt + 2 * tq) =
                    make_float2(d[mt][0][2] + d[mt][1][2] + b3.x, d[mt][0][3] + d[mt][1][3] + b3.y);
        }
    }
}

extern "C" void kernel_launch(void* const* d_in, const int* in_sizes, int n_in,
                              void* d_out, int out_size)
{
    const float* t   = (const float*)d_in[0];
    const float* emb = (const float*)d_in[1];
    const float* pa  = (const float*)d_in[3];
    const float* Wt1 = (const float*)d_in[9];
    const float* bt1 = (const float*)d_in[10];
    const float* Wt2 = (const float*)d_in[11];
    const float* bt2 = (const float*)d_in[12];
    const float* Wd1 = (const float*)d_in[13];
    const float* bd1 = (const float*)d_in[14];
    const float* Wd2 = (const float*)d_in[15];
    const float* bd2 = (const float*)d_in[16];
    const float* Wd3 = (const float*)d_in[17];
    const float* bd3 = (const float*)d_in[18];
    float* out = (float*)d_out;

    const int nrows = in_sizes[1] / HID;

    velo_kernel<<<(nrows + 127) / 128, TPB>>>(emb, t, pa, Wt1, bt1, Wt2, bt2,
                                              Wd1, bd1, Wd2, bd2, Wd3, bd3,
                                              out, nrows);
}

// round 14
// speedup vs baseline: 1.1023x; 1.1023x over previous
#include <cuda_runtime.h>
#include <cuda_bf16.h>
#include <cstdint>

// velocity = MLP(concat(zone_embedding, person_attrs, time_vec)).
// GCN layers are dead code w.r.t. the output; person/time layer-1
// contributions are row-constant, folded into c1 in-kernel.
//
// R14: single kernel, TPB=256 (8 warps, 256 rows/block -> half the blocks,
// packing amortized 2x). Two-stage packing: coalesced raw-W LDG.128 -> smem,
// then scatter via LDS (4-way conflict ~0.25us vs R11's 1.2us of scattered-
// LDG L1 wavefronts), split2, STS frags. Mainloop = R12's exactly (bf16
// 3-term-split mma.m16n8k16, merged accumulators — R13's split regressed).

#define HID 32
#define H1  64
#define TPB 256            // 8 warps, 32 rows/warp, 256 rows/block

typedef uint32_t u32;

// pack pair (x0 -> low half, x1 -> high half) into bf16x2 hi, residual lo.
__device__ __forceinline__ void split2(float x0, float x1, u32& hi, u32& lo) {
    asm("cvt.rn.bf16x2.f32 %0, %1, %2;" : "=r"(hi) : "f"(x1), "f"(x0));
    float h0 = __uint_as_float(hi << 16);
    float h1 = __uint_as_float(hi & 0xffff0000u);
    float r0 = x0 - h0;
    float r1 = x1 - h1;
    asm("cvt.rn.bf16x2.f32 %0, %1, %2;" : "=r"(lo) : "f"(r1), "f"(r0));
}

__device__ __forceinline__ void mma_bf16(float d[4], const u32 a[4], u32 b0, u32 b1) {
    asm("mma.sync.aligned.m16n8k16.row.col.f32.bf16.bf16.f32 "
        "{%0,%1,%2,%3}, {%4,%5,%6,%7}, {%8,%9}, {%0,%1,%2,%3};"
        : "+f"(d[0]), "+f"(d[1]), "+f"(d[2]), "+f"(d[3])
        : "r"(a[0]), "r"(a[1]), "r"(a[2]), "r"(a[3]), "r"(b0), "r"(b1));
}

// ---------------------------------------------------------------------------
__global__ void __launch_bounds__(TPB, 2)
velo_kernel(const float* __restrict__ emb,
            const float* __restrict__ t,   const float* __restrict__ pa,
            const float* __restrict__ Wt1, const float* __restrict__ bt1,
            const float* __restrict__ Wt2, const float* __restrict__ bt2,
            const float* __restrict__ Wd1, const float* __restrict__ bd1,
            const float* __restrict__ Wd2, const float* __restrict__ bd2,
            const float* __restrict__ Wd3, const float* __restrict__ bd3,
            float* __restrict__ out, int nrows)
{
    __shared__ __align__(16) float s_raw[5120];     // 20KB raw W1|W2|W3
    __shared__ __align__(16) uint4 s_frag[1280];    // 20KB packed B-frags
    __shared__ __align__(16) float s_c1[64];
    __shared__ float s_u[16], s_tv[16];

    const int tid  = threadIdx.x;
    const int warp = tid >> 5;
    const int lane = tid & 31;
    const int g = lane >> 2, tq = lane & 3;
    const int row_base = blockIdx.x * 256 + warp * 32;

    // ---- A1 fragments up front (independent of packing; R12-proven regs) ----
    const float2 zero2 = make_float2(0.0f, 0.0f);
    int ra[2], rb[2];
    #pragma unroll
    for (int mt = 0; mt < 2; ++mt) { ra[mt] = row_base + 16 * mt + g; rb[mt] = ra[mt] + 8; }

    u32 A1h[2][2][4], A1l[2][2][4];
    if (row_base < nrows) {
        #pragma unroll
        for (int mt = 0; mt < 2; ++mt) {
            #pragma unroll
            for (int kt = 0; kt < 2; ++kt) {
                float2 p0 = (ra[mt] < nrows) ? *reinterpret_cast<const float2*>(emb + (size_t)ra[mt] * 32 + 16 * kt + 2 * tq)     : zero2;
                float2 p1 = (rb[mt] < nrows) ? *reinterpret_cast<const float2*>(emb + (size_t)rb[mt] * 32 + 16 * kt + 2 * tq)     : zero2;
                float2 p2 = (ra[mt] < nrows) ? *reinterpret_cast<const float2*>(emb + (size_t)ra[mt] * 32 + 16 * kt + 8 + 2 * tq) : zero2;
                float2 p3 = (rb[mt] < nrows) ? *reinterpret_cast<const float2*>(emb + (size_t)rb[mt] * 32 + 16 * kt + 8 + 2 * tq) : zero2;
                split2(p0.x, p0.y, A1h[mt][kt][0], A1l[mt][kt][0]);
                split2(p1.x, p1.y, A1h[mt][kt][1], A1l[mt][kt][1]);
                split2(p2.x, p2.y, A1h[mt][kt][2], A1l[mt][kt][2]);
                split2(p3.x, p3.y, A1h[mt][kt][3], A1l[mt][kt][3]);
            }
        }
    }

    // ---- phase 1: coalesced raw weights -> smem; u fold ----
    {
        const float4* w1v = reinterpret_cast<const float4*>(Wd1);  // zone rows: first 512 f4
        const float4* w2v = reinterpret_cast<const float4*>(Wd2);
        const float4* w3v = reinterpret_cast<const float4*>(Wd3);
        float4* rw = reinterpret_cast<float4*>(s_raw);
        #pragma unroll
        for (int i = tid; i < 512; i += TPB)  rw[i]        = w1v[i];
        #pragma unroll
        for (int i = tid; i < 512; i += TPB)  rw[512 + i]  = w2v[i];
        #pragma unroll
        for (int i = tid; i < 256; i += TPB)  rw[1024 + i] = w3v[i];
    }
    if (tid < 16) s_u[tid] = fmaxf(fmaf(t[0], Wt1[tid], bt1[tid]), 0.0f);
    __syncthreads();

    // ---- phase 2: pack frags (LDS scatter -> split2 -> STS); tv fold ----
    if (tid < 16) {
        float a = bt2[tid];
        #pragma unroll
        for (int i = 0; i < 16; i++) a = fmaf(s_u[i], Wt2[i * 16 + tid], a);
        s_tv[tid] = a;
    }
    #pragma unroll
    for (int p = 0; p < 5; ++p) {
        int idx = tid + p * TPB;
        int base, stride, nt, kt, ln;
        if (idx < 512)       { int s = idx;        ln = s & 31; int q = s >> 5; nt = q >> 1; kt = q & 1; base = 0;    stride = 64; }
        else if (idx < 1024) { int s = idx - 512;  ln = s & 31; int q = s >> 5; nt = q >> 2; kt = q & 3; base = 2048; stride = 32; }
        else                 { int s = idx - 1024; ln = s & 31; int q = s >> 5; nt = q >> 1; kt = q & 1; base = 4096; stride = 32; }
        int gg = ln >> 2, tt = ln & 3;
        int col  = 8 * nt + gg;
        int krow = 16 * kt + 2 * tt;
        float w00 = s_raw[base + (krow    ) * stride + col];
        float w01 = s_raw[base + (krow + 1) * stride + col];
        float w10 = s_raw[base + (krow + 8) * stride + col];
        float w11 = s_raw[base + (krow + 9) * stride + col];
        uint4 f;
        split2(w00, w01, f.x, f.z);
        split2(w10, w11, f.y, f.w);
        s_frag[idx] = f;
    }
    __syncthreads();

    // ---- phase 3: c1 fold ----
    if (tid < H1) {
        float a = bd1[tid];
        #pragma unroll
        for (int p = 0; p < 8; p++)  a = fmaf(pa[p], Wd1[(HID + p) * H1 + tid], a);
        #pragma unroll
        for (int i = 0; i < 16; i++) a = fmaf(s_tv[i], Wd1[(HID + 8 + i) * H1 + tid], a);
        s_c1[tid] = a;
    }
    __syncthreads();

    if (row_base >= nrows) return;      // after the last barrier

    // ---- layer1 (K=32, N=64): nt-outer, both m-tiles per B fragment ----
    u32 A2h[2][4][4], A2l[2][4][4];
    #pragma unroll
    for (int nt = 0; nt < 8; ++nt) {
        float d[2][4] = {{0.f,0.f,0.f,0.f},{0.f,0.f,0.f,0.f}};
        #pragma unroll
        for (int kt = 0; kt < 2; ++kt) {
            uint4 B = s_frag[(nt * 2 + kt) * 32 + lane];
            #pragma unroll
            for (int mt = 0; mt < 2; ++mt) {
                mma_bf16(d[mt], A1h[mt][kt], B.x, B.y);
                mma_bf16(d[mt], A1h[mt][kt], B.z, B.w);
                mma_bf16(d[mt], A1l[mt][kt], B.x, B.y);
            }
        }
        float2 cb = *reinterpret_cast<const float2*>(s_c1 + 8 * nt + 2 * tq);
        int kt2 = nt >> 1, off = (nt & 1) * 2;
        #pragma unroll
        for (int mt = 0; mt < 2; ++mt) {
            float h0 = fmaxf(d[mt][0] + cb.x, 0.0f);
            float h1 = fmaxf(d[mt][1] + cb.y, 0.0f);
            float h2 = fmaxf(d[mt][2] + cb.x, 0.0f);
            float h3 = fmaxf(d[mt][3] + cb.y, 0.0f);
            split2(h0, h1, A2h[mt][kt2][off],     A2l[mt][kt2][off]);
            split2(h2, h3, A2h[mt][kt2][off + 1], A2l[mt][kt2][off + 1]);
        }
    }

    // ---- layer2 (K=64, N=32) ----
    u32 A3h[2][2][4], A3l[2][2][4];
    #pragma unroll
    for (int nt = 0; nt < 4; ++nt) {
        float d[2][4] = {{0.f,0.f,0.f,0.f},{0.f,0.f,0.f,0.f}};
        #pragma unroll
        for (int kt = 0; kt < 4; ++kt) {
            uint4 B = s_frag[512 + (nt * 4 + kt) * 32 + lane];
            #pragma unroll
            for (int mt = 0; mt < 2; ++mt) {
                mma_bf16(d[mt], A2h[mt][kt], B.x, B.y);
                mma_bf16(d[mt], A2h[mt][kt], B.z, B.w);
                mma_bf16(d[mt], A2l[mt][kt], B.x, B.y);
            }
        }
        float2 bb = *reinterpret_cast<const float2*>(bd2 + 8 * nt + 2 * tq);
        int kt3 = nt >> 1, off = (nt & 1) * 2;
        #pragma unroll
        for (int mt = 0; mt < 2; ++mt) {
            float h0 = fmaxf(d[mt][0] + bb.x, 0.0f);
            float h1 = fmaxf(d[mt][1] + bb.y, 0.0f);
            float h2 = fmaxf(d[mt][2] + bb.x, 0.0f);
            float h3 = fmaxf(d[mt][3] + bb.y, 0.0f);
            split2(h0, h1, A3h[mt][kt3][off],     A3l[mt][kt3][off]);
            split2(h2, h3, A3h[mt][kt3][off + 1], A3l[mt][kt3][off + 1]);
        }
    }

    // ---- layer3 (K=32, N=32) + bias, store ----
    #pragma unroll
    for (int nt = 0; nt < 4; ++nt) {
        float d[2][4] = {{0.f,0.f,0.f,0.f},{0.f,0.f,0.f,0.f}};
        #pragma unroll
        for (int kt = 0; kt < 2; ++kt) {
            uint4 B = s_frag[1024 + (nt * 2 + kt) * 32 + lane];
            #pragma unroll
            for (int mt = 0; mt < 2; ++mt) {
                mma_bf16(d[mt], A3h[mt][kt], B.x, B.y);
                mma_bf16(d[mt], A3h[mt][kt], B.z, B.w);
                mma_bf16(d[mt], A3l[mt][kt], B.x, B.y);
            }
        }
        float2 b3 = *reinterpret_cast<const float2*>(bd3 + 8 * nt + 2 * tq);
        #pragma unroll
        for (int mt = 0; mt < 2; ++mt) {
            if (ra[mt] < nrows)
                *reinterpret_cast<float2*>(out + (size_t)ra[mt] * 32 + 8 * nt + 2 * tq) = make_float2(d[mt][0] + b3.x, d[mt][1] + b3.y);
            if (rb[mt] < nrows)
                *reinterpret_cast<float2*>(out + (size_t)rb[mt] * 32 + 8 * nt + 2 * tq) = make_float2(d[mt][2] + b3.x, d[mt][3] + b3.y);
        }
    }
}

extern "C" void kernel_launch(void* const* d_in, const int* in_sizes, int n_in,
                              void* d_out, int out_size)
{
    const float* t   = (const float*)d_in[0];
    const float* emb = (const float*)d_in[1];
    const float* pa  = (const float*)d_in[3];
    const float* Wt1 = (const float*)d_in[9];
    const float* bt1 = (const float*)d_in[10];
    const float* Wt2 = (const float*)d_in[11];
    const float* bt2 = (const float*)d_in[12];
    const float* Wd1 = (const float*)d_in[13];
    const float* bd1 = (const float*)d_in[14];
    const float* Wd2 = (const float*)d_in[15];
    const float* bd2 = (const float*)d_in[16];
    const float* Wd3 = (const float*)d_in[17];
    const float* bd3 = (const float*)d_in[18];
    float* out = (float*)d_out;

    const int nrows = in_sizes[1] / HID;

    velo_kernel<<<(nrows + 255) / 256, TPB>>>(emb, t, pa, Wt1, bt1, Wt2, bt2,
                                              Wd1, bd1, Wd2, bd2, Wd3, bd3,
                                              out, nrows);
}